// round 1
// baseline (speedup 1.0000x reference)
#include <cuda_runtime.h>
#include <cstdint>

#define NN 50000
#define EE 800000
#define GG 500
#define DD 128
#define NCH 49   // ceil((NN+1)/1024)

// ---------------- device scratch (no allocations allowed) ----------------
__device__ int    d_off[NN + 1];
__device__ int    d_cursor[NN];
__device__ int    d_bsum[64];
__device__ float4 d_erec[EE];           // {src_as_float, ea0, ea1, ea2} sorted by dst
__device__ float  d_bufA[NN * DD];      // agg + x  (GEMM1 input)
__device__ float  d_bufH[NN * DD];      // h (pre-BN)
__device__ float  d_bufX[NN * DD];      // layer output / next layer input
__device__ float  d_bufA9[NN * 16];     // layer0 agg (din=9, stride 16)
__device__ float  d_colsum[DD];
__device__ float  d_colsq[DD];
__device__ float  d_alpha[DD];
__device__ float  d_beta[DD];
__device__ int    d_gstart[GG + 1];

// ---------------- CSR build ----------------
__global__ void k_init() {
    int i = blockIdx.x * blockDim.x + threadIdx.x;
    if (i < NN + 1) d_off[i] = 0;
    if (i <= GG) d_gstart[i] = NN;
}

__global__ void k_hist(const int* __restrict__ dst) {
    int e = blockIdx.x * blockDim.x + threadIdx.x;
    if (e < EE) atomicAdd(&d_off[dst[e] + 1], 1);
}

__global__ void k_scan1() {
    __shared__ int s[1024];
    int t = threadIdx.x;
    int i = blockIdx.x * 1024 + t;
    int v = (i < NN + 1) ? d_off[i] : 0;
    s[t] = v;
    __syncthreads();
    for (int ofs = 1; ofs < 1024; ofs <<= 1) {
        int u = (t >= ofs) ? s[t - ofs] : 0;
        __syncthreads();
        s[t] += u;
        __syncthreads();
    }
    if (i < NN + 1) d_off[i] = s[t];
    if (t == 1023) d_bsum[blockIdx.x] = s[1023];
}

__global__ void k_scan2() {
    int run = 0;
    for (int i = 0; i < NCH; i++) { int v = d_bsum[i]; d_bsum[i] = run; run += v; }
}

__global__ void k_scan3() {
    int i = blockIdx.x * 1024 + threadIdx.x;
    if (i < NN + 1) {
        int v = d_off[i] + d_bsum[blockIdx.x];
        d_off[i] = v;
        if (i < NN) d_cursor[i] = v;
    }
}

__global__ void k_scatter(const int* __restrict__ src, const int* __restrict__ dst,
                          const float* __restrict__ ea) {
    int e = blockIdx.x * blockDim.x + threadIdx.x;
    if (e >= EE) return;
    int p = atomicAdd(&d_cursor[dst[e]], 1);
    d_erec[p] = make_float4(__int_as_float(src[e]), ea[e * 3], ea[e * 3 + 1], ea[e * 3 + 2]);
}

// ---------------- graph boundaries (batch is sorted) ----------------
__global__ void k_gstart(const int* __restrict__ batch) {
    int n = blockIdx.x * blockDim.x + threadIdx.x;
    if (n < NN) atomicMin(&d_gstart[batch[n]], n);
}

__global__ void k_gfix() {
    for (int g = GG - 1; g >= 0; g--)
        if (d_gstart[g] == NN) d_gstart[g] = d_gstart[g + 1];
}

// ---------------- aggregation: agg+x, din=9 (layer 0) ----------------
__global__ void k_agg9(const float* __restrict__ xin, const float* __restrict__ We,
                       const float* __restrict__ be) {
    int gw = (blockIdx.x * blockDim.x + threadIdx.x) >> 5;
    int lane = threadIdx.x & 31;
    if (gw >= NN) return;
    float w0 = 0.f, w1 = 0.f, w2 = 0.f, bb = 0.f;
    if (lane < 9) { w0 = We[lane * 3]; w1 = We[lane * 3 + 1]; w2 = We[lane * 3 + 2]; bb = be[lane]; }
    float acc = 0.f;
    int e0 = d_off[gw], e1 = d_off[gw + 1];
    for (int e = e0; e < e1; e++) {
        float4 r = __ldg(&d_erec[e]);
        int s = __float_as_int(r.x);
        if (lane < 9) {
            float xs = __ldg(xin + (size_t)s * 9 + lane);
            acc += fmaxf(xs + fmaf(w0, r.y, fmaf(w1, r.z, fmaf(w2, r.w, bb))), 0.f);
        }
    }
    if (lane < 9) d_bufA9[gw * 16 + lane] = xin[(size_t)gw * 9 + lane] + acc;
}

// ---------------- aggregation: agg+x, din=128 (layers 1,2). reads d_bufX ----------------
__global__ void k_agg128(const float* __restrict__ We, const float* __restrict__ be) {
    int gw = (blockIdx.x * blockDim.x + threadIdx.x) >> 5;
    int lane = threadIdx.x & 31;
    if (gw >= NN) return;
    const float* xin = d_bufX;
    int f = lane * 4;
    float w00 = We[(f + 0) * 3], w01 = We[(f + 0) * 3 + 1], w02 = We[(f + 0) * 3 + 2];
    float w10 = We[(f + 1) * 3], w11 = We[(f + 1) * 3 + 1], w12 = We[(f + 1) * 3 + 2];
    float w20 = We[(f + 2) * 3], w21 = We[(f + 2) * 3 + 1], w22 = We[(f + 2) * 3 + 2];
    float w30 = We[(f + 3) * 3], w31 = We[(f + 3) * 3 + 1], w32 = We[(f + 3) * 3 + 2];
    float b0 = be[f + 0], b1 = be[f + 1], b2 = be[f + 2], b3 = be[f + 3];
    float a0 = 0.f, a1 = 0.f, a2 = 0.f, a3 = 0.f;
    int e0 = d_off[gw], e1 = d_off[gw + 1];
    for (int e = e0; e < e1; e++) {
        float4 r = __ldg(&d_erec[e]);
        int s = __float_as_int(r.x);
        float4 xs = __ldg((const float4*)(xin + (size_t)s * DD + f));
        a0 += fmaxf(xs.x + fmaf(w00, r.y, fmaf(w01, r.z, fmaf(w02, r.w, b0))), 0.f);
        a1 += fmaxf(xs.y + fmaf(w10, r.y, fmaf(w11, r.z, fmaf(w12, r.w, b1))), 0.f);
        a2 += fmaxf(xs.z + fmaf(w20, r.y, fmaf(w21, r.z, fmaf(w22, r.w, b2))), 0.f);
        a3 += fmaxf(xs.w + fmaf(w30, r.y, fmaf(w31, r.z, fmaf(w32, r.w, b3))), 0.f);
    }
    float4 xn = *(const float4*)(xin + (size_t)gw * DD + f);
    float4 o = make_float4(xn.x + a0, xn.y + a1, xn.z + a2, xn.w + a3);
    *(float4*)(d_bufA + (size_t)gw * DD + f) = o;
}

// ---------------- BN helpers ----------------
__global__ void k_zero_stats() {
    int d = threadIdx.x;
    d_colsum[d] = 0.f;
    d_colsq[d] = 0.f;
}

__global__ void k_bn(const float* __restrict__ g, const float* __restrict__ b) {
    int d = threadIdx.x;
    float inv_n = 1.0f / (float)NN;
    float mu = d_colsum[d] * inv_n;
    float var = d_colsq[d] * inv_n - mu * mu;
    float a = g[d] * rsqrtf(var + 1e-5f);
    d_alpha[d] = a;
    d_beta[d] = fmaf(-mu, a, b[d]);
}

// ---------------- GEMM1 for layer0 (din=9): h = bufA9 @ W1^T, with BN stats ----------------
__global__ void k_gemm9(const float* __restrict__ W1) {
    __shared__ float sA[64][17];
    int d = threadIdx.x;  // 128 threads = output columns
    float w[9];
#pragma unroll
    for (int k = 0; k < 9; k++) w[k] = W1[d * 9 + k];
    int r0 = blockIdx.x * 64;
    for (int i = d; i < 64 * 16; i += 128) {
        int rr = i >> 4, cc = i & 15;
        int r = r0 + rr;
        sA[rr][cc] = (r < NN && cc < 9) ? d_bufA9[r * 16 + cc] : 0.f;
    }
    __syncthreads();
    float cs = 0.f, cq = 0.f;
    int rmax = min(64, NN - r0);
    for (int rr = 0; rr < rmax; rr++) {
        float h = 0.f;
#pragma unroll
        for (int k = 0; k < 9; k++) h = fmaf(sA[rr][k], w[k], h);
        d_bufH[(size_t)(r0 + rr) * DD + d] = h;
        cs += h;
        cq += h * h;
    }
    atomicAdd(&d_colsum[d], cs);
    atomicAdd(&d_colsq[d], cq);
}

// ---------------- tiled 128-K GEMM ----------------
// MODE 0: C(d_bufH) = A(d_bufA) @ W^T, accumulate column stats of C
// MODE 1: C(d_bufX) = relu( relu(alpha*A(d_bufH)+beta) @ W^T + bias )
template <int MODE>
__global__ void __launch_bounds__(256, 2) k_gemm(const float* __restrict__ Wm,
                                                 const float* __restrict__ bias) {
    __shared__ float As[32][132];
    __shared__ float Ws[32][132];
    const float* A = (MODE == 0) ? d_bufA : d_bufH;
    float* C = (MODE == 0) ? d_bufH : d_bufX;

    int tid = threadIdx.x;
    int tx = tid & 15, ty = tid >> 4;
    int rowBase = blockIdx.x * 128;

    float acc[8][8];
#pragma unroll
    for (int i = 0; i < 8; i++)
#pragma unroll
        for (int j = 0; j < 8; j++) acc[i][j] = 0.f;

    for (int kt = 0; kt < 128; kt += 32) {
#pragma unroll
        for (int it = 0; it < 4; it++) {
            int idx = tid + it * 256;   // 0..1023
            int r = idx >> 3;           // 0..127
            int q = idx & 7;            // 0..7
            int k = kt + q * 4;
            int rg = rowBase + r;
            float4 v = (rg < NN) ? *(const float4*)(A + (size_t)rg * DD + k)
                                 : make_float4(0.f, 0.f, 0.f, 0.f);
            if (MODE == 1) {
                float4 al = *(const float4*)(&d_alpha[k]);
                float4 be = *(const float4*)(&d_beta[k]);
                v.x = fmaxf(fmaf(v.x, al.x, be.x), 0.f);
                v.y = fmaxf(fmaf(v.y, al.y, be.y), 0.f);
                v.z = fmaxf(fmaf(v.z, al.z, be.z), 0.f);
                v.w = fmaxf(fmaf(v.w, al.w, be.w), 0.f);
            }
            As[q * 4 + 0][r] = v.x;
            As[q * 4 + 1][r] = v.y;
            As[q * 4 + 2][r] = v.z;
            As[q * 4 + 3][r] = v.w;
            float4 wv = *(const float4*)(Wm + (size_t)r * DD + k);
            Ws[q * 4 + 0][r] = wv.x;
            Ws[q * 4 + 1][r] = wv.y;
            Ws[q * 4 + 2][r] = wv.z;
            Ws[q * 4 + 3][r] = wv.w;
        }
        __syncthreads();
#pragma unroll
        for (int k = 0; k < 32; k++) {
            float a[8], w[8];
            *(float4*)(a + 0) = *(const float4*)&As[k][ty * 8];
            *(float4*)(a + 4) = *(const float4*)&As[k][ty * 8 + 4];
            *(float4*)(w + 0) = *(const float4*)&Ws[k][tx * 8];
            *(float4*)(w + 4) = *(const float4*)&Ws[k][tx * 8 + 4];
#pragma unroll
            for (int i = 0; i < 8; i++)
#pragma unroll
                for (int j = 0; j < 8; j++) acc[i][j] = fmaf(a[i], w[j], acc[i][j]);
        }
        __syncthreads();
    }

    // epilogue
    float bj[8];
    if (MODE == 1) {
#pragma unroll
        for (int j = 0; j < 8; j++) bj[j] = bias[tx * 8 + j];
    }
    float csum[8], csq[8];
#pragma unroll
    for (int j = 0; j < 8; j++) { csum[j] = 0.f; csq[j] = 0.f; }

#pragma unroll
    for (int i = 0; i < 8; i++) {
        int rg = rowBase + ty * 8 + i;
        if (rg >= NN) break;
        float vrow[8];
#pragma unroll
        for (int j = 0; j < 8; j++) {
            float v = acc[i][j];
            if (MODE == 1) v = fmaxf(v + bj[j], 0.f);
            vrow[j] = v;
            if (MODE == 0) { csum[j] += v; csq[j] += v * v; }
        }
        *(float4*)(C + (size_t)rg * DD + tx * 8) = *(float4*)(vrow);
        *(float4*)(C + (size_t)rg * DD + tx * 8 + 4) = *(float4*)(vrow + 4);
    }

    if (MODE == 0) {
        __syncthreads();
        float* red = &As[0][0];  // 4224 floats >= 16*128
#pragma unroll
        for (int j = 0; j < 8; j++) red[ty * 128 + tx * 8 + j] = csum[j];
        __syncthreads();
        if (tid < 128) {
            float s = 0.f;
            for (int t = 0; t < 16; t++) s += red[t * 128 + tid];
            atomicAdd(&d_colsum[tid], s);
        }
        __syncthreads();
#pragma unroll
        for (int j = 0; j < 8; j++) red[ty * 128 + tx * 8 + j] = csq[j];
        __syncthreads();
        if (tid < 128) {
            float s = 0.f;
            for (int t = 0; t < 16; t++) s += red[t * 128 + tid];
            atomicAdd(&d_colsq[tid], s);
        }
    }
}

// ---------------- pooling (contiguous ranges, batch is sorted) ----------------
__global__ void k_pool(float* __restrict__ out, int coff) {
    int g = blockIdx.x, d = threadIdx.x;
    int n0 = d_gstart[g], n1 = d_gstart[g + 1];
    float s = 0.f;
    for (int n = n0; n < n1; n++) s += d_bufX[(size_t)n * DD + d];
    out[(size_t)g * 384 + coff + d] = s;
}

// ---------------- launch ----------------
extern "C" void kernel_launch(void* const* d_in, const int* in_sizes, int n_in,
                              void* d_out, int out_size) {
    const float* x = (const float*)d_in[0];
    const int* ei = (const int*)d_in[1];
    const float* ea = (const float*)d_in[2];
    const int* batch = (const int*)d_in[3];
    const float* P[21];
    for (int i = 0; i < 21; i++) P[i] = (const float*)d_in[4 + i];
    float* out = (float*)d_out;
    const int* src = ei;
    const int* dst = ei + EE;

    // CSR + graph boundaries (shared by all 3 layers)
    k_init<<<(NN + 1 + 255) / 256, 256>>>();
    k_hist<<<(EE + 255) / 256, 256>>>(dst);
    k_scan1<<<NCH, 1024>>>();
    k_scan2<<<1, 1>>>();
    k_scan3<<<NCH, 1024>>>();
    k_scatter<<<(EE + 255) / 256, 256>>>(src, dst, ea);
    k_gstart<<<(NN + 255) / 256, 256>>>(batch);
    k_gfix<<<1, 1>>>();

    const int gemm_grid = (NN + 127) / 128;  // 391

    // ---- layer 0 (din = 9) ----
    k_agg9<<<(NN + 7) / 8, 256>>>(x, P[0], P[1]);
    k_zero_stats<<<1, 128>>>();
    k_gemm9<<<(NN + 63) / 64, 128>>>(P[2]);
    k_bn<<<1, 128>>>(P[3], P[4]);
    k_gemm<1><<<gemm_grid, 256>>>(P[5], P[6]);
    k_pool<<<GG, 128>>>(out, 0);

    // ---- layers 1, 2 (din = 128) ----
    for (int l = 1; l < 3; l++) {
        const float* const* Q = P + 7 * l;
        k_agg128<<<(NN + 7) / 8, 256>>>(Q[0], Q[1]);
        k_zero_stats<<<1, 128>>>();
        k_gemm<0><<<gemm_grid, 256>>>(Q[2], nullptr);
        k_bn<<<1, 128>>>(Q[3], Q[4]);
        k_gemm<1><<<gemm_grid, 256>>>(Q[5], Q[6]);
        k_pool<<<GG, 128>>>(out, 128 * l);
    }
}

// round 2
// speedup vs baseline: 1.0290x; 1.0290x over previous
#include <cuda_runtime.h>
#include <cstdint>

#define NN 50000
#define EE 800000
#define GG 500
#define DD 128
#define NCH 49   // ceil((NN+1)/1024)

// ---------------- device scratch (no allocations allowed) ----------------
__device__ int    d_off[NN + 1];
__device__ int    d_cursor[NN];
__device__ int    d_bsum[64];
__device__ float4 d_erec[EE];           // {src_as_float, ea0, ea1, ea2} sorted by dst
__device__ float  d_bufA[NN * DD];      // agg + x  (GEMM1 input)
__device__ float  d_bufH[NN * DD];      // h (pre-BN)
__device__ float  d_bufX[NN * DD];      // layer output / next layer input
__device__ float  d_bufA9[NN * 16];     // layer0 agg (din=9, stride 16)
__device__ float  d_colsum[DD];
__device__ float  d_colsq[DD];
__device__ float  d_alpha[DD];
__device__ float  d_beta[DD];
__device__ int    d_gstart[GG + 1];

// ---------------- packed fp32 FMA helpers (sm_103a FFMA2) ----------------
__device__ __forceinline__ void ffma2(float2& c, const float2& a, const float2& b) {
    asm("fma.rn.f32x2 %0, %1, %2, %0;"
        : "+l"(*reinterpret_cast<unsigned long long*>(&c))
        : "l"(*reinterpret_cast<const unsigned long long*>(&a)),
          "l"(*reinterpret_cast<const unsigned long long*>(&b)));
}
__device__ __forceinline__ float2 dup2(float a) {
    float2 r;
    asm("mov.b64 %0, {%1, %1};"
        : "=l"(*reinterpret_cast<unsigned long long*>(&r))
        : "f"(a));
    return r;
}

// ---------------- CSR build ----------------
__global__ void k_init() {
    int i = blockIdx.x * blockDim.x + threadIdx.x;
    if (i < NN + 1) d_off[i] = 0;
    if (i <= GG) d_gstart[i] = NN;
    if (i < DD) { d_colsum[i] = 0.f; d_colsq[i] = 0.f; }
}

__global__ void k_hist(const int* __restrict__ dst) {
    int e = blockIdx.x * blockDim.x + threadIdx.x;
    if (e < EE) atomicAdd(&d_off[dst[e] + 1], 1);
}

__global__ void k_scan1() {
    __shared__ int s[1024];
    int t = threadIdx.x;
    int i = blockIdx.x * 1024 + t;
    int v = (i < NN + 1) ? d_off[i] : 0;
    s[t] = v;
    __syncthreads();
    for (int ofs = 1; ofs < 1024; ofs <<= 1) {
        int u = (t >= ofs) ? s[t - ofs] : 0;
        __syncthreads();
        s[t] += u;
        __syncthreads();
    }
    if (i < NN + 1) d_off[i] = s[t];
    if (t == 1023) d_bsum[blockIdx.x] = s[1023];
}

// also fixes graph-boundary sentinels (k_gstart ran earlier)
__global__ void k_scan2() {
    int run = 0;
    for (int i = 0; i < NCH; i++) { int v = d_bsum[i]; d_bsum[i] = run; run += v; }
    for (int g = GG - 1; g >= 0; g--)
        if (d_gstart[g] == NN) d_gstart[g] = d_gstart[g + 1];
}

__global__ void k_scan3() {
    int i = blockIdx.x * 1024 + threadIdx.x;
    if (i < NN + 1) {
        int v = d_off[i] + d_bsum[blockIdx.x];
        d_off[i] = v;
        if (i < NN) d_cursor[i] = v;
    }
}

__global__ void k_scatter(const int* __restrict__ src, const int* __restrict__ dst,
                          const float* __restrict__ ea) {
    int e = blockIdx.x * blockDim.x + threadIdx.x;
    if (e >= EE) return;
    int p = atomicAdd(&d_cursor[dst[e]], 1);
    d_erec[p] = make_float4(__int_as_float(src[e]), ea[e * 3], ea[e * 3 + 1], ea[e * 3 + 2]);
}

// ---------------- graph boundaries (batch is sorted) ----------------
__global__ void k_gstart(const int* __restrict__ batch) {
    int n = blockIdx.x * blockDim.x + threadIdx.x;
    if (n < NN) atomicMin(&d_gstart[batch[n]], n);
}

// ---------------- aggregation: agg+x, din=9 (layer 0) ----------------
__global__ void k_agg9(const float* __restrict__ xin, const float* __restrict__ We,
                       const float* __restrict__ be) {
    int gw = (blockIdx.x * blockDim.x + threadIdx.x) >> 5;
    int lane = threadIdx.x & 31;
    if (gw >= NN) return;
    float w0 = 0.f, w1 = 0.f, w2 = 0.f, bb = 0.f;
    if (lane < 9) { w0 = We[lane * 3]; w1 = We[lane * 3 + 1]; w2 = We[lane * 3 + 2]; bb = be[lane]; }
    float acc = 0.f;
    int e0 = d_off[gw], e1 = d_off[gw + 1];
    for (int e = e0; e < e1; e++) {
        float4 r = __ldg(&d_erec[e]);
        int s = __float_as_int(r.x);
        if (lane < 9) {
            float xs = __ldg(xin + (size_t)s * 9 + lane);
            acc += fmaxf(xs + fmaf(w0, r.y, fmaf(w1, r.z, fmaf(w2, r.w, bb))), 0.f);
        }
    }
    if (lane < 9) d_bufA9[gw * 16 + lane] = xin[(size_t)gw * 9 + lane] + acc;
}

// ---------------- aggregation: agg+x, din=128 (layers 1,2). reads d_bufX ----------------
__global__ void k_agg128(const float* __restrict__ We, const float* __restrict__ be) {
    int gw = (blockIdx.x * blockDim.x + threadIdx.x) >> 5;
    int lane = threadIdx.x & 31;
    if (gw >= NN) return;
    const float* xin = d_bufX;
    int f = lane * 4;
    float w00 = We[(f + 0) * 3], w01 = We[(f + 0) * 3 + 1], w02 = We[(f + 0) * 3 + 2];
    float w10 = We[(f + 1) * 3], w11 = We[(f + 1) * 3 + 1], w12 = We[(f + 1) * 3 + 2];
    float w20 = We[(f + 2) * 3], w21 = We[(f + 2) * 3 + 1], w22 = We[(f + 2) * 3 + 2];
    float w30 = We[(f + 3) * 3], w31 = We[(f + 3) * 3 + 1], w32 = We[(f + 3) * 3 + 2];
    float b0 = be[f + 0], b1 = be[f + 1], b2 = be[f + 2], b3 = be[f + 3];
    float a0 = 0.f, a1 = 0.f, a2 = 0.f, a3 = 0.f;
    int e0 = d_off[gw], e1 = d_off[gw + 1];
    for (int e = e0; e < e1; e++) {
        float4 r = __ldg(&d_erec[e]);
        int s = __float_as_int(r.x);
        float4 xs = __ldg((const float4*)(xin + (size_t)s * DD + f));
        a0 += fmaxf(xs.x + fmaf(w00, r.y, fmaf(w01, r.z, fmaf(w02, r.w, b0))), 0.f);
        a1 += fmaxf(xs.y + fmaf(w10, r.y, fmaf(w11, r.z, fmaf(w12, r.w, b1))), 0.f);
        a2 += fmaxf(xs.z + fmaf(w20, r.y, fmaf(w21, r.z, fmaf(w22, r.w, b2))), 0.f);
        a3 += fmaxf(xs.w + fmaf(w30, r.y, fmaf(w31, r.z, fmaf(w32, r.w, b3))), 0.f);
    }
    float4 xn = *(const float4*)(xin + (size_t)gw * DD + f);
    float4 o = make_float4(xn.x + a0, xn.y + a1, xn.z + a2, xn.w + a3);
    *(float4*)(d_bufA + (size_t)gw * DD + f) = o;
}

// ---------------- BN: fold stats into per-column affine; reset stats for next layer ----------------
__global__ void k_bn(const float* __restrict__ g, const float* __restrict__ b) {
    int d = threadIdx.x;
    float inv_n = 1.0f / (float)NN;
    float mu = d_colsum[d] * inv_n;
    float var = d_colsq[d] * inv_n - mu * mu;
    float a = g[d] * rsqrtf(var + 1e-5f);
    d_alpha[d] = a;
    d_beta[d] = fmaf(-mu, a, b[d]);
    d_colsum[d] = 0.f;
    d_colsq[d] = 0.f;
}

// ---------------- GEMM1 for layer0 (din=9): h = bufA9 @ W1^T, with BN stats ----------------
__global__ void k_gemm9(const float* __restrict__ W1) {
    __shared__ float sA[64][17];
    int d = threadIdx.x;  // 128 threads = output columns
    float w[9];
#pragma unroll
    for (int k = 0; k < 9; k++) w[k] = W1[d * 9 + k];
    int r0 = blockIdx.x * 64;
    for (int i = d; i < 64 * 16; i += 128) {
        int rr = i >> 4, cc = i & 15;
        int r = r0 + rr;
        sA[rr][cc] = (r < NN && cc < 9) ? d_bufA9[r * 16 + cc] : 0.f;
    }
    __syncthreads();
    float cs = 0.f, cq = 0.f;
    int rmax = min(64, NN - r0);
    for (int rr = 0; rr < rmax; rr++) {
        float h = 0.f;
#pragma unroll
        for (int k = 0; k < 9; k++) h = fmaf(sA[rr][k], w[k], h);
        d_bufH[(size_t)(r0 + rr) * DD + d] = h;
        cs += h;
        cq += h * h;
    }
    atomicAdd(&d_colsum[d], cs);
    atomicAdd(&d_colsq[d], cq);
}

// ---------------- tiled 128-K GEMM with packed f32x2 FMA ----------------
// MODE 0: C(d_bufH) = A(d_bufA) @ W^T, accumulate column stats of C
// MODE 1: C(d_bufX) = relu( relu(alpha*A(d_bufH)+beta) @ W^T + bias )
template <int MODE>
__global__ void __launch_bounds__(256, 2) k_gemm(const float* __restrict__ Wm,
                                                 const float* __restrict__ bias) {
    __shared__ float As[32][132];
    __shared__ float Ws[32][132];
    const float* A = (MODE == 0) ? d_bufA : d_bufH;
    float* C = (MODE == 0) ? d_bufH : d_bufX;

    int tid = threadIdx.x;
    int tx = tid & 15, ty = tid >> 4;
    int rowBase = blockIdx.x * 128;

    float2 acc2[8][4];
#pragma unroll
    for (int i = 0; i < 8; i++)
#pragma unroll
        for (int jp = 0; jp < 4; jp++) acc2[i][jp] = make_float2(0.f, 0.f);

    for (int kt = 0; kt < 128; kt += 32) {
#pragma unroll
        for (int it = 0; it < 4; it++) {
            int idx = tid + it * 256;   // 0..1023
            int r = idx >> 3;           // 0..127
            int q = idx & 7;            // 0..7
            int k = kt + q * 4;
            int rg = rowBase + r;
            float4 v = (rg < NN) ? *(const float4*)(A + (size_t)rg * DD + k)
                                 : make_float4(0.f, 0.f, 0.f, 0.f);
            if (MODE == 1) {
                float4 al = *(const float4*)(&d_alpha[k]);
                float4 be = *(const float4*)(&d_beta[k]);
                v.x = fmaxf(fmaf(v.x, al.x, be.x), 0.f);
                v.y = fmaxf(fmaf(v.y, al.y, be.y), 0.f);
                v.z = fmaxf(fmaf(v.z, al.z, be.z), 0.f);
                v.w = fmaxf(fmaf(v.w, al.w, be.w), 0.f);
            }
            As[q * 4 + 0][r] = v.x;
            As[q * 4 + 1][r] = v.y;
            As[q * 4 + 2][r] = v.z;
            As[q * 4 + 3][r] = v.w;
            float4 wv = *(const float4*)(Wm + (size_t)r * DD + k);
            Ws[q * 4 + 0][r] = wv.x;
            Ws[q * 4 + 1][r] = wv.y;
            Ws[q * 4 + 2][r] = wv.z;
            Ws[q * 4 + 3][r] = wv.w;
        }
        __syncthreads();
#pragma unroll
        for (int k = 0; k < 32; k++) {
            float a[8];
            float2 wp[4];
            *(float4*)(a + 0) = *(const float4*)&As[k][ty * 8];
            *(float4*)(a + 4) = *(const float4*)&As[k][ty * 8 + 4];
            *(float4*)(&wp[0]) = *(const float4*)&Ws[k][tx * 8];
            *(float4*)(&wp[2]) = *(const float4*)&Ws[k][tx * 8 + 4];
#pragma unroll
            for (int i = 0; i < 8; i++) {
                float2 aa = dup2(a[i]);
#pragma unroll
                for (int jp = 0; jp < 4; jp++) ffma2(acc2[i][jp], aa, wp[jp]);
            }
        }
        __syncthreads();
    }

    // epilogue
    float bj[8];
    if (MODE == 1) {
#pragma unroll
        for (int j = 0; j < 8; j++) bj[j] = bias[tx * 8 + j];
    }
    float csum[8], csq[8];
#pragma unroll
    for (int j = 0; j < 8; j++) { csum[j] = 0.f; csq[j] = 0.f; }

#pragma unroll
    for (int i = 0; i < 8; i++) {
        int rg = rowBase + ty * 8 + i;
        if (rg >= NN) break;
        float vrow[8];
#pragma unroll
        for (int j = 0; j < 8; j++) {
            float v = (j & 1) ? acc2[i][j >> 1].y : acc2[i][j >> 1].x;
            if (MODE == 1) v = fmaxf(v + bj[j], 0.f);
            vrow[j] = v;
            if (MODE == 0) { csum[j] += v; csq[j] += v * v; }
        }
        *(float4*)(C + (size_t)rg * DD + tx * 8) = *(float4*)(vrow);
        *(float4*)(C + (size_t)rg * DD + tx * 8 + 4) = *(float4*)(vrow + 4);
    }

    if (MODE == 0) {
        __syncthreads();
        float* red = &As[0][0];  // 4224 floats >= 16*128
#pragma unroll
        for (int j = 0; j < 8; j++) red[ty * 128 + tx * 8 + j] = csum[j];
        __syncthreads();
        if (tid < 128) {
            float s = 0.f;
            for (int t = 0; t < 16; t++) s += red[t * 128 + tid];
            atomicAdd(&d_colsum[tid], s);
        }
        __syncthreads();
#pragma unroll
        for (int j = 0; j < 8; j++) red[ty * 128 + tx * 8 + j] = csq[j];
        __syncthreads();
        if (tid < 128) {
            float s = 0.f;
            for (int t = 0; t < 16; t++) s += red[t * 128 + tid];
            atomicAdd(&d_colsq[tid], s);
        }
    }
}

// ---------------- pooling (contiguous ranges, batch is sorted) ----------------
__global__ void k_pool(float* __restrict__ out, int coff) {
    int g = blockIdx.x, d = threadIdx.x;
    int n0 = d_gstart[g], n1 = d_gstart[g + 1];
    float s = 0.f;
    for (int n = n0; n < n1; n++) s += d_bufX[(size_t)n * DD + d];
    out[(size_t)g * 384 + coff + d] = s;
}

// ---------------- launch ----------------
extern "C" void kernel_launch(void* const* d_in, const int* in_sizes, int n_in,
                              void* d_out, int out_size) {
    const float* x = (const float*)d_in[0];
    const int* ei = (const int*)d_in[1];
    const float* ea = (const float*)d_in[2];
    const int* batch = (const int*)d_in[3];
    const float* P[21];
    for (int i = 0; i < 21; i++) P[i] = (const float*)d_in[4 + i];
    float* out = (float*)d_out;
    const int* src = ei;
    const int* dst = ei + EE;

    // CSR + graph boundaries (shared by all 3 layers)
    k_init<<<(NN + 1 + 255) / 256, 256>>>();
    k_gstart<<<(NN + 255) / 256, 256>>>(batch);
    k_hist<<<(EE + 255) / 256, 256>>>(dst);
    k_scan1<<<NCH, 1024>>>();
    k_scan2<<<1, 1>>>();           // also fixes d_gstart sentinels
    k_scan3<<<NCH, 1024>>>();
    k_scatter<<<(EE + 255) / 256, 256>>>(src, dst, ea);

    const int gemm_grid = (NN + 127) / 128;  // 391

    // ---- layer 0 (din = 9) ----
    k_agg9<<<(NN + 7) / 8, 256>>>(x, P[0], P[1]);
    k_gemm9<<<(NN + 63) / 64, 128>>>(P[2]);
    k_bn<<<1, 128>>>(P[3], P[4]);
    k_gemm<1><<<gemm_grid, 256>>>(P[5], P[6]);
    k_pool<<<GG, 128>>>(out, 0);

    // ---- layers 1, 2 (din = 128) ----
    for (int l = 1; l < 3; l++) {
        const float* const* Q = P + 7 * l;
        k_agg128<<<(NN + 7) / 8, 256>>>(Q[0], Q[1]);
        k_gemm<0><<<gemm_grid, 256>>>(Q[2], nullptr);
        k_bn<<<1, 128>>>(Q[3], Q[4]);
        k_gemm<1><<<gemm_grid, 256>>>(Q[5], Q[6]);
        k_pool<<<GG, 128>>>(out, 128 * l);
    }
}

// round 5
// speedup vs baseline: 1.1553x; 1.1227x over previous
#include <cuda_runtime.h>
#include <cstdint>

#define NN 50000
#define EE 800000
#define GG 500
#define DD 128
#define NCH 49   // ceil((NN+1)/1024)

// ---------------- device scratch (no allocations allowed) ----------------
__device__ int    d_off[NN + 1];
__device__ int    d_cursor[NN];
__device__ int    d_bsum[64];
__device__ float4 d_erec[EE];           // {src_as_float, ea0, ea1, ea2} sorted by dst
__device__ float  d_bufA[NN * DD];      // agg + x  (GEMM1 input)
__device__ float  d_bufH[NN * DD];      // h (pre-BN)
__device__ float  d_bufX[NN * DD];      // layer output / next layer input
__device__ float  d_bufA9[NN * 16];     // layer0 agg (din=9, stride 16)
__device__ float  d_colsum[DD];
__device__ float  d_colsq[DD];
__device__ float  d_alpha[DD];
__device__ float  d_beta[DD];
__device__ int    d_gstart[GG + 1];

// ---------------- helpers ----------------
__device__ __forceinline__ uint32_t smem_u32(const void* p) {
    uint32_t a;
    asm("{ .reg .u64 t; cvta.to.shared.u64 t, %1; cvt.u32.u64 %0, t; }" : "=r"(a) : "l"(p));
    return a;
}
// pack two fp32 into bf16x2 (first arg -> lower half)
__device__ __forceinline__ uint32_t pkbf(float lo, float hi) {
    uint32_t r;
    asm("cvt.rn.satfinite.bf16x2.f32 %0, %1, %2;" : "=r"(r) : "f"(hi), "f"(lo));
    return r;
}
__device__ __forceinline__ float unlo(uint32_t p) { return __uint_as_float(p << 16); }
__device__ __forceinline__ float unhi(uint32_t p) { return __uint_as_float(p & 0xFFFF0000u); }
__device__ __forceinline__ void sts32(uint32_t a, uint32_t v) {
    asm volatile("st.shared.b32 [%0], %1;" :: "r"(a), "r"(v) : "memory");
}
__device__ __forceinline__ void ldsm4(uint32_t* r, uint32_t addr) {
    asm volatile("ldmatrix.sync.aligned.m8n8.x4.shared.b16 {%0,%1,%2,%3}, [%4];"
                 : "=r"(r[0]), "=r"(r[1]), "=r"(r[2]), "=r"(r[3]) : "r"(addr));
}
__device__ __forceinline__ void mma_bf16(float* c, const uint32_t* a, const uint32_t* b) {
    asm volatile(
        "mma.sync.aligned.m16n8k16.row.col.f32.bf16.bf16.f32 "
        "{%0,%1,%2,%3}, {%4,%5,%6,%7}, {%8,%9}, {%0,%1,%2,%3};"
        : "+f"(c[0]), "+f"(c[1]), "+f"(c[2]), "+f"(c[3])
        : "r"(a[0]), "r"(a[1]), "r"(a[2]), "r"(a[3]), "r"(b[0]), "r"(b[1]));
}
// XOR swizzle for 256B rows: rotate 16B slots by row%8
__device__ __forceinline__ uint32_t swz(uint32_t off) {
    return off ^ (((off >> 8) & 7) << 4);
}

// ---------------- CSR build ----------------
__global__ void k_init() {
    int i = blockIdx.x * blockDim.x + threadIdx.x;
    if (i < NN + 1) d_off[i] = 0;
    if (i <= GG) d_gstart[i] = NN;
    if (i < DD) { d_colsum[i] = 0.f; d_colsq[i] = 0.f; }
}

__global__ void k_hist(const int* __restrict__ dst) {
    int e = blockIdx.x * blockDim.x + threadIdx.x;
    if (e < EE) atomicAdd(&d_off[dst[e] + 1], 1);
}

__global__ void k_scan1() {
    __shared__ int s[1024];
    int t = threadIdx.x;
    int i = blockIdx.x * 1024 + t;
    int v = (i < NN + 1) ? d_off[i] : 0;
    s[t] = v;
    __syncthreads();
    for (int ofs = 1; ofs < 1024; ofs <<= 1) {
        int u = (t >= ofs) ? s[t - ofs] : 0;
        __syncthreads();
        s[t] += u;
        __syncthreads();
    }
    if (i < NN + 1) d_off[i] = s[t];
    if (t == 1023) d_bsum[blockIdx.x] = s[1023];
}

__global__ void k_scan2() {
    int run = 0;
    for (int i = 0; i < NCH; i++) { int v = d_bsum[i]; d_bsum[i] = run; run += v; }
    for (int g = GG - 1; g >= 0; g--)
        if (d_gstart[g] == NN) d_gstart[g] = d_gstart[g + 1];
}

__global__ void k_scan3() {
    int i = blockIdx.x * 1024 + threadIdx.x;
    if (i < NN + 1) {
        int v = d_off[i] + d_bsum[blockIdx.x];
        d_off[i] = v;
        if (i < NN) d_cursor[i] = v;
    }
}

__global__ void k_scatter(const int* __restrict__ src, const int* __restrict__ dst,
                          const float* __restrict__ ea) {
    int e = blockIdx.x * blockDim.x + threadIdx.x;
    if (e >= EE) return;
    int p = atomicAdd(&d_cursor[dst[e]], 1);
    d_erec[p] = make_float4(__int_as_float(src[e]), ea[e * 3], ea[e * 3 + 1], ea[e * 3 + 2]);
}

__global__ void k_gstart(const int* __restrict__ batch) {
    int n = blockIdx.x * blockDim.x + threadIdx.x;
    if (n < NN) atomicMin(&d_gstart[batch[n]], n);
}

// ---------------- aggregation: agg+x, din=9 (layer 0) ----------------
__global__ void k_agg9(const float* __restrict__ xin, const float* __restrict__ We,
                       const float* __restrict__ be) {
    int gw = (blockIdx.x * blockDim.x + threadIdx.x) >> 5;
    int lane = threadIdx.x & 31;
    if (gw >= NN) return;
    float w0 = 0.f, w1 = 0.f, w2 = 0.f, bb = 0.f;
    if (lane < 9) { w0 = We[lane * 3]; w1 = We[lane * 3 + 1]; w2 = We[lane * 3 + 2]; bb = be[lane]; }
    float acc = 0.f;
    int e0 = d_off[gw], e1 = d_off[gw + 1];
    for (int e = e0; e < e1; e++) {
        float4 r = __ldg(&d_erec[e]);
        int s = __float_as_int(r.x);
        if (lane < 9) {
            float xs = __ldg(xin + (size_t)s * 9 + lane);
            acc += fmaxf(xs + fmaf(w0, r.y, fmaf(w1, r.z, fmaf(w2, r.w, bb))), 0.f);
        }
    }
    if (lane < 9) d_bufA9[gw * 16 + lane] = xin[(size_t)gw * 9 + lane] + acc;
}

// ---------------- aggregation: agg+x, din=128 (layers 1,2). reads d_bufX ----------------
__global__ void k_agg128(const float* __restrict__ We, const float* __restrict__ be) {
    int gw = (blockIdx.x * blockDim.x + threadIdx.x) >> 5;
    int lane = threadIdx.x & 31;
    if (gw >= NN) return;
    const float* xin = d_bufX;
    int f = lane * 4;
    float w00 = We[(f + 0) * 3], w01 = We[(f + 0) * 3 + 1], w02 = We[(f + 0) * 3 + 2];
    float w10 = We[(f + 1) * 3], w11 = We[(f + 1) * 3 + 1], w12 = We[(f + 1) * 3 + 2];
    float w20 = We[(f + 2) * 3], w21 = We[(f + 2) * 3 + 1], w22 = We[(f + 2) * 3 + 2];
    float w30 = We[(f + 3) * 3], w31 = We[(f + 3) * 3 + 1], w32 = We[(f + 3) * 3 + 2];
    float b0 = be[f + 0], b1 = be[f + 1], b2 = be[f + 2], b3 = be[f + 3];
    float a0 = 0.f, a1 = 0.f, a2 = 0.f, a3 = 0.f;
    int e0 = d_off[gw], e1 = d_off[gw + 1];
    for (int e = e0; e < e1; e++) {
        float4 r = __ldg(&d_erec[e]);
        int s = __float_as_int(r.x);
        float4 xs = __ldg((const float4*)(xin + (size_t)s * DD + f));
        a0 += fmaxf(xs.x + fmaf(w00, r.y, fmaf(w01, r.z, fmaf(w02, r.w, b0))), 0.f);
        a1 += fmaxf(xs.y + fmaf(w10, r.y, fmaf(w11, r.z, fmaf(w12, r.w, b1))), 0.f);
        a2 += fmaxf(xs.z + fmaf(w20, r.y, fmaf(w21, r.z, fmaf(w22, r.w, b2))), 0.f);
        a3 += fmaxf(xs.w + fmaf(w30, r.y, fmaf(w31, r.z, fmaf(w32, r.w, b3))), 0.f);
    }
    float4 xn = *(const float4*)(xin + (size_t)gw * DD + f);
    float4 o = make_float4(xn.x + a0, xn.y + a1, xn.z + a2, xn.w + a3);
    *(float4*)(d_bufA + (size_t)gw * DD + f) = o;
}

// ---------------- BN: fold stats into per-column affine; reset stats ----------------
__global__ void k_bn(const float* __restrict__ g, const float* __restrict__ b) {
    int d = threadIdx.x;
    float inv_n = 1.0f / (float)NN;
    float mu = d_colsum[d] * inv_n;
    float var = d_colsq[d] * inv_n - mu * mu;
    float a = g[d] * rsqrtf(var + 1e-5f);
    d_alpha[d] = a;
    d_beta[d] = fmaf(-mu, a, b[d]);
    d_colsum[d] = 0.f;
    d_colsq[d] = 0.f;
}

// ---------------- column stats of d_bufH (for MODE-0 GEMM output) ----------------
__global__ void k_stats() {
    int d = threadIdx.x;  // column
    float s = 0.f, q = 0.f;
    for (int r = blockIdx.x; r < NN; r += gridDim.x) {
        float v = d_bufH[(size_t)r * DD + d];
        s += v;
        q += v * v;
    }
    atomicAdd(&d_colsum[d], s);
    atomicAdd(&d_colsq[d], q);
}

// ---------------- GEMM1 for layer0 (din=9): h = bufA9 @ W1^T, with BN stats ----------------
__global__ void k_gemm9(const float* __restrict__ W1) {
    __shared__ float sA[64][17];
    int d = threadIdx.x;
    float w[9];
#pragma unroll
    for (int k = 0; k < 9; k++) w[k] = W1[d * 9 + k];
    int r0 = blockIdx.x * 64;
    for (int i = d; i < 64 * 16; i += 128) {
        int rr = i >> 4, cc = i & 15;
        int r = r0 + rr;
        sA[rr][cc] = (r < NN && cc < 9) ? d_bufA9[r * 16 + cc] : 0.f;
    }
    __syncthreads();
    float cs = 0.f, cq = 0.f;
    int rmax = min(64, NN - r0);
    for (int rr = 0; rr < rmax; rr++) {
        float h = 0.f;
#pragma unroll
        for (int k = 0; k < 9; k++) h = fmaf(sA[rr][k], w[k], h);
        d_bufH[(size_t)(r0 + rr) * DD + d] = h;
        cs += h;
        cq += h * h;
    }
    atomicAdd(&d_colsum[d], cs);
    atomicAdd(&d_colsq[d], cq);
}

// ---------------- bf16-split tensor-core GEMM (mma.sync m16n8k16) ----------------
// 128x128 output tile per block, K = 128. 8 warps in 4(m) x 2(n) grid:
// each warp computes 32 rows x 64 cols. D = Ah*Bh + Ah*Bl + Al*Bh (fp32 acc).
// MODE 0: bufH = bufA @ W^T
// MODE 1: bufX = relu( relu(alpha*bufH+beta) @ W^T + bias )
#define SMEM_MMA (4 * 32768 + 1024)

template <int MODE>
__global__ void __launch_bounds__(256, 1) k_mma(const float* __restrict__ Wm,
                                                const float* __restrict__ bias) {
    extern __shared__ char dynsm[];
    uint32_t sb = (smem_u32(dynsm) + 1023) & ~1023u;
    uint32_t AH = sb, AL = sb + 32768, BH = sb + 65536, BL = sb + 98304;

    const float* A = (MODE == 0) ? d_bufA : d_bufH;
    float* C = (MODE == 0) ? d_bufH : d_bufX;

    int tid = threadIdx.x;
    int warp = tid >> 5, lane = tid & 31;
    int rowBase = blockIdx.x * 128;

    // ---- convert A (fp32 -> bf16 hi/lo, swizzled [128][128] bf16 rows) ----
    // 128 rows x 32 quads = 4096 elements, 256 threads -> 16 passes
#pragma unroll
    for (int it = 0; it < 16; it++) {
        int idx = tid + it * 256;
        int r = idx >> 5, quad = idx & 31;  // quad -> 4 floats
        int rg = rowBase + r;
        float4 v = (rg < NN) ? *(const float4*)(A + (size_t)rg * DD + quad * 4)
                             : make_float4(0.f, 0.f, 0.f, 0.f);
        if (MODE == 1) {
            float4 al4 = *(const float4*)(&d_alpha[quad * 4]);
            float4 be4 = *(const float4*)(&d_beta[quad * 4]);
            v.x = fmaxf(fmaf(v.x, al4.x, be4.x), 0.f);
            v.y = fmaxf(fmaf(v.y, al4.y, be4.y), 0.f);
            v.z = fmaxf(fmaf(v.z, al4.z, be4.z), 0.f);
            v.w = fmaxf(fmaf(v.w, al4.w, be4.w), 0.f);
        }
        uint32_t sa = swz((uint32_t)(r * 256 + quad * 8));
        uint32_t h0 = pkbf(v.x, v.y), h1 = pkbf(v.z, v.w);
        uint32_t l0 = pkbf(v.x - unlo(h0), v.y - unhi(h0));
        uint32_t l1 = pkbf(v.z - unlo(h1), v.w - unhi(h1));
        sts32(AH + sa, h0); sts32(AH + sa + 4, h1);
        sts32(AL + sa, l0); sts32(AL + sa + 4, l1);
    }
    // ---- convert W [128 out(n)][128 in(k)] ----
#pragma unroll
    for (int it = 0; it < 16; it++) {
        int idx = tid + it * 256;
        int r = idx >> 5, quad = idx & 31;
        float4 v = *(const float4*)(Wm + (size_t)r * DD + quad * 4);
        uint32_t sa = swz((uint32_t)(r * 256 + quad * 8));
        uint32_t h0 = pkbf(v.x, v.y), h1 = pkbf(v.z, v.w);
        uint32_t l0 = pkbf(v.x - unlo(h0), v.y - unhi(h0));
        uint32_t l1 = pkbf(v.z - unlo(h1), v.w - unhi(h1));
        sts32(BH + sa, h0); sts32(BH + sa + 4, h1);
        sts32(BL + sa, l0); sts32(BL + sa + 4, l1);
    }
    __syncthreads();

    int m0 = (warp >> 1) * 32;   // 0,32,64,96
    int n0 = (warp & 1) * 64;    // 0,64

    float acc[2][8][4];
#pragma unroll
    for (int mt = 0; mt < 2; mt++)
#pragma unroll
        for (int nt = 0; nt < 8; nt++)
#pragma unroll
            for (int j = 0; j < 4; j++) acc[mt][nt][j] = 0.f;

    int mi = lane >> 3, ri = lane & 7;
    // per-lane fixed parts of ldmatrix addresses
    int arow = m0 + (mi & 1) * 8 + ri;           // + mt*16
    uint32_t axor = (uint32_t)((arow & 7) << 4);
    int akc = (mi >> 1) * 8;                     // + k0
    int brow = n0 + (mi >> 1) * 8 + ri;          // + nt2*16
    uint32_t bxor = (uint32_t)((brow & 7) << 4);
    int bkc = (mi & 1) * 8;                      // + k0

#pragma unroll
    for (int kc = 0; kc < 8; kc++) {
        int k0 = kc * 16;
        uint32_t aH[2][4], aL[2][4];
#pragma unroll
        for (int mt = 0; mt < 2; mt++) {
            uint32_t off = (uint32_t)((arow + mt * 16) * 256) +
                           (((uint32_t)((k0 + akc) * 2)) ^ axor);
            ldsm4(aH[mt], AH + off);
            ldsm4(aL[mt], AL + off);
        }
        uint32_t bHf[8][2], bLf[8][2];
#pragma unroll
        for (int nt2 = 0; nt2 < 4; nt2++) {
            uint32_t off = (uint32_t)((brow + nt2 * 16) * 256) +
                           (((uint32_t)((k0 + bkc) * 2)) ^ bxor);
            uint32_t t[4];
            ldsm4(t, BH + off);
            bHf[nt2 * 2][0] = t[0]; bHf[nt2 * 2][1] = t[1];
            bHf[nt2 * 2 + 1][0] = t[2]; bHf[nt2 * 2 + 1][1] = t[3];
            ldsm4(t, BL + off);
            bLf[nt2 * 2][0] = t[0]; bLf[nt2 * 2][1] = t[1];
            bLf[nt2 * 2 + 1][0] = t[2]; bLf[nt2 * 2 + 1][1] = t[3];
        }
#pragma unroll
        for (int mt = 0; mt < 2; mt++)
#pragma unroll
            for (int nt = 0; nt < 8; nt++) {
                mma_bf16(acc[mt][nt], aH[mt], bHf[nt]);
                mma_bf16(acc[mt][nt], aH[mt], bLf[nt]);
                mma_bf16(acc[mt][nt], aL[mt], bHf[nt]);
            }
    }

    // ---- epilogue ----
    int g = lane >> 2, cpair = (lane & 3) * 2;
#pragma unroll
    for (int mt = 0; mt < 2; mt++) {
#pragma unroll
        for (int half = 0; half < 2; half++) {
            int rg = rowBase + m0 + mt * 16 + g + half * 8;
            if (rg >= NN) continue;
#pragma unroll
            for (int nt = 0; nt < 8; nt++) {
                int col = n0 + nt * 8 + cpair;
                float v0 = acc[mt][nt][half * 2 + 0];
                float v1 = acc[mt][nt][half * 2 + 1];
                if (MODE == 1) {
                    v0 = fmaxf(v0 + __ldg(bias + col), 0.f);
                    v1 = fmaxf(v1 + __ldg(bias + col + 1), 0.f);
                }
                *(float2*)(C + (size_t)rg * DD + col) = make_float2(v0, v1);
            }
        }
    }
}

// ---------------- pooling (contiguous ranges, batch is sorted) ----------------
__global__ void k_pool(float* __restrict__ out, int coff) {
    int g = blockIdx.x, d = threadIdx.x;
    int n0 = d_gstart[g], n1 = d_gstart[g + 1];
    float s = 0.f;
    for (int n = n0; n < n1; n++) s += d_bufX[(size_t)n * DD + d];
    out[(size_t)g * 384 + coff + d] = s;
}

// ---------------- launch ----------------
extern "C" void kernel_launch(void* const* d_in, const int* in_sizes, int n_in,
                              void* d_out, int out_size) {
    const float* x = (const float*)d_in[0];
    const int* ei = (const int*)d_in[1];
    const float* ea = (const float*)d_in[2];
    const int* batch = (const int*)d_in[3];
    const float* P[21];
    for (int i = 0; i < 21; i++) P[i] = (const float*)d_in[4 + i];
    float* out = (float*)d_out;
    const int* src = ei;
    const int* dst = ei + EE;

    cudaFuncSetAttribute(k_mma<0>, cudaFuncAttributeMaxDynamicSharedMemorySize, SMEM_MMA);
    cudaFuncSetAttribute(k_mma<1>, cudaFuncAttributeMaxDynamicSharedMemorySize, SMEM_MMA);

    // CSR + graph boundaries (shared by all 3 layers)
    k_init<<<(NN + 1 + 255) / 256, 256>>>();
    k_gstart<<<(NN + 255) / 256, 256>>>(batch);
    k_hist<<<(EE + 255) / 256, 256>>>(dst);
    k_scan1<<<NCH, 1024>>>();
    k_scan2<<<1, 1>>>();           // also fixes d_gstart sentinels
    k_scan3<<<NCH, 1024>>>();
    k_scatter<<<(EE + 255) / 256, 256>>>(src, dst, ea);

    const int mma_grid = (NN + 127) / 128;  // 391

    // ---- layer 0 (din = 9) ----
    k_agg9<<<(NN + 7) / 8, 256>>>(x, P[0], P[1]);
    k_gemm9<<<(NN + 63) / 64, 128>>>(P[2]);
    k_bn<<<1, 128>>>(P[3], P[4]);
    k_mma<1><<<mma_grid, 256, SMEM_MMA>>>(P[5], P[6]);
    k_pool<<<GG, 128>>>(out, 0);

    // ---- layers 1, 2 (din = 128) ----
    for (int l = 1; l < 3; l++) {
        const float* const* Q = P + 7 * l;
        k_agg128<<<(NN + 7) / 8, 256>>>(Q[0], Q[1]);
        k_mma<0><<<mma_grid, 256, SMEM_MMA>>>(Q[2], nullptr);
        k_stats<<<296, 128>>>();
        k_bn<<<1, 128>>>(Q[3], Q[4]);
        k_mma<1><<<mma_grid, 256, SMEM_MMA>>>(Q[5], Q[6]);
        k_pool<<<GG, 128>>>(out, 128 * l);
    }
}

// round 7
// speedup vs baseline: 1.4208x; 1.2298x over previous
#include <cuda_runtime.h>
#include <cstdint>

#define NN 50000
#define EE 800000
#define GG 500
#define DD 128
#define NCH 49   // ceil((NN+1)/1024)

// ---------------- device scratch (no allocations allowed) ----------------
__device__ int      d_off[NN + 1];
__device__ int      d_cursor[NN];
__device__ int      d_bsum[64];
__device__ float4   d_erec[EE];          // {src_as_float, ea0, ea1, ea2} sorted by dst
__device__ float    d_bufA[NN * DD];     // agg + x  (GEMM1 input)
__device__ float    d_bufH[NN * DD];     // h (pre-BN)
__device__ float    d_bufX0[NN * DD];    // layer outputs
__device__ float    d_bufX1[NN * DD];
__device__ float    d_bufX2[NN * DD];
__device__ float    d_bufA9[NN * 16];    // layer0 agg (din=9, stride 16)
__device__ float    d_colsum[DD];
__device__ float    d_colsq[DD];
__device__ float    d_alpha[DD];
__device__ float    d_beta[DD];
__device__ int      d_gstart[GG + 1];
__device__ uint32_t d_WH[5 * 8192];      // W bf16-hi, swizzled tile layout
__device__ uint32_t d_WL[5 * 8192];      // W bf16-lo

// device-side buffer selector (NEVER pass __device__ symbols from host!)
__device__ __forceinline__ float* bufsel(int i) {
    switch (i) {
        case 0: return d_bufA;
        case 1: return d_bufH;
        case 2: return d_bufX0;
        case 3: return d_bufX1;
        default: return d_bufX2;
    }
}

// ---------------- helpers ----------------
__device__ __forceinline__ uint32_t smem_u32(const void* p) {
    uint32_t a;
    asm("{ .reg .u64 t; cvta.to.shared.u64 t, %1; cvt.u32.u64 %0, t; }" : "=r"(a) : "l"(p));
    return a;
}
__device__ __forceinline__ uint32_t pkbf(float lo, float hi) {
    uint32_t r;
    asm("cvt.rn.satfinite.bf16x2.f32 %0, %1, %2;" : "=r"(r) : "f"(hi), "f"(lo));
    return r;
}
__device__ __forceinline__ float unlo(uint32_t p) { return __uint_as_float(p << 16); }
__device__ __forceinline__ float unhi(uint32_t p) { return __uint_as_float(p & 0xFFFF0000u); }
__device__ __forceinline__ void sts32(uint32_t a, uint32_t v) {
    asm volatile("st.shared.b32 [%0], %1;" :: "r"(a), "r"(v) : "memory");
}
__device__ __forceinline__ void sts128(uint32_t a, uint4 v) {
    asm volatile("st.shared.v4.b32 [%0], {%1,%2,%3,%4};"
                 :: "r"(a), "r"(v.x), "r"(v.y), "r"(v.z), "r"(v.w) : "memory");
}
__device__ __forceinline__ void ldsm4(uint32_t* r, uint32_t addr) {
    asm volatile("ldmatrix.sync.aligned.m8n8.x4.shared.b16 {%0,%1,%2,%3}, [%4];"
                 : "=r"(r[0]), "=r"(r[1]), "=r"(r[2]), "=r"(r[3]) : "r"(addr));
}
__device__ __forceinline__ void mma_bf16(float* c, const uint32_t* a, const uint32_t* b) {
    asm volatile(
        "mma.sync.aligned.m16n8k16.row.col.f32.bf16.bf16.f32 "
        "{%0,%1,%2,%3}, {%4,%5,%6,%7}, {%8,%9}, {%0,%1,%2,%3};"
        : "+f"(c[0]), "+f"(c[1]), "+f"(c[2]), "+f"(c[3])
        : "r"(a[0]), "r"(a[1]), "r"(a[2]), "r"(a[3]), "r"(b[0]), "r"(b[1]));
}
// XOR swizzle for 256B rows: rotate 16B slots by row%8
__device__ __forceinline__ uint32_t swz(uint32_t off) {
    return off ^ (((off >> 8) & 7) << 4);
}

// ---------------- CSR build ----------------
__global__ void k_init() {
    int i = blockIdx.x * blockDim.x + threadIdx.x;
    if (i < NN + 1) d_off[i] = 0;
    if (i < DD) { d_colsum[i] = 0.f; d_colsq[i] = 0.f; }
}

__global__ void k_hist(const int* __restrict__ dst) {
    int e = blockIdx.x * blockDim.x + threadIdx.x;
    if (e < EE) atomicAdd(&d_off[dst[e] + 1], 1);
}

__global__ void k_scan1() {
    __shared__ int s[1024];
    int t = threadIdx.x;
    int i = blockIdx.x * 1024 + t;
    int v = (i < NN + 1) ? d_off[i] : 0;
    s[t] = v;
    __syncthreads();
    for (int ofs = 1; ofs < 1024; ofs <<= 1) {
        int u = (t >= ofs) ? s[t - ofs] : 0;
        __syncthreads();
        s[t] += u;
        __syncthreads();
    }
    if (i < NN + 1) d_off[i] = s[t];
    if (t == 1023) d_bsum[blockIdx.x] = s[1023];
}

__global__ void k_scan2() {
    int run = 0;
    for (int i = 0; i < NCH; i++) { int v = d_bsum[i]; d_bsum[i] = run; run += v; }
}

__global__ void k_scan3() {
    int i = blockIdx.x * 1024 + threadIdx.x;
    if (i < NN + 1) {
        int v = d_off[i] + d_bsum[blockIdx.x];
        d_off[i] = v;
        if (i < NN) d_cursor[i] = v;
    }
}

__global__ void k_scatter(const int* __restrict__ src, const int* __restrict__ dst,
                          const float* __restrict__ ea) {
    int e = blockIdx.x * blockDim.x + threadIdx.x;
    if (e >= EE) return;
    int p = atomicAdd(&d_cursor[dst[e]], 1);
    d_erec[p] = make_float4(__int_as_float(src[e]), ea[e * 3], ea[e * 3 + 1], ea[e * 3 + 2]);
}

// graph boundaries via parallel binary search (batch is sorted; handles empty graphs)
__global__ void k_gbound(const int* __restrict__ batch) {
    int g = threadIdx.x;
    if (g > GG) return;
    int lo = 0, hi = NN;
    while (lo < hi) {
        int mid = (lo + hi) >> 1;
        if (batch[mid] < g) lo = mid + 1; else hi = mid;
    }
    d_gstart[g] = lo;
}

// ---------------- W precompute: fp32 -> bf16 hi/lo, swizzled tile layout ----------------
__global__ void k_wconv(const float* __restrict__ W0, const float* __restrict__ W1,
                        const float* __restrict__ W2, const float* __restrict__ W3,
                        const float* __restrict__ W4) {
    const float* Ws[5] = {W0, W1, W2, W3, W4};
    const float* W = Ws[blockIdx.x];
    uint32_t* oh = d_WH + blockIdx.x * 8192;
    uint32_t* ol = d_WL + blockIdx.x * 8192;
    int tid = threadIdx.x;
#pragma unroll
    for (int it = 0; it < 16; it++) {
        int idx = tid + it * 256;
        int r = idx >> 5, quad = idx & 31;
        float4 v = *(const float4*)(W + (size_t)r * DD + quad * 4);
        uint32_t sa = swz((uint32_t)(r * 256 + quad * 8)) >> 2;  // uint32 index
        uint32_t h0 = pkbf(v.x, v.y), h1 = pkbf(v.z, v.w);
        uint32_t l0 = pkbf(v.x - unlo(h0), v.y - unhi(h0));
        uint32_t l1 = pkbf(v.z - unlo(h1), v.w - unhi(h1));
        oh[sa] = h0; oh[sa + 1] = h1;
        ol[sa] = l0; ol[sa + 1] = l1;
    }
}

// ---------------- aggregation: agg+x, din=9 (layer 0) ----------------
__global__ void k_agg9(const float* __restrict__ xin, const float* __restrict__ We,
                       const float* __restrict__ be) {
    int gw = (blockIdx.x * blockDim.x + threadIdx.x) >> 5;
    int lane = threadIdx.x & 31;
    if (gw >= NN) return;
    float w0 = 0.f, w1 = 0.f, w2 = 0.f, bb = 0.f;
    if (lane < 9) { w0 = We[lane * 3]; w1 = We[lane * 3 + 1]; w2 = We[lane * 3 + 2]; bb = be[lane]; }
    float acc = 0.f;
    int e0 = d_off[gw], e1 = d_off[gw + 1];
    for (int e = e0; e < e1; e++) {
        float4 r = __ldg(&d_erec[e]);
        int s = __float_as_int(r.x);
        if (lane < 9) {
            float xs = __ldg(xin + (size_t)s * 9 + lane);
            acc += fmaxf(xs + fmaf(w0, r.y, fmaf(w1, r.z, fmaf(w2, r.w, bb))), 0.f);
        }
    }
    if (lane < 9) d_bufA9[gw * 16 + lane] = xin[(size_t)gw * 9 + lane] + acc;
}

// ---------------- aggregation: agg+x, din=128 (layers 1,2); xin/out via bufsel ----------------
__global__ void k_agg128(int xbuf, const float* __restrict__ We, const float* __restrict__ be) {
    int gw = (blockIdx.x * blockDim.x + threadIdx.x) >> 5;
    int lane = threadIdx.x & 31;
    if (gw >= NN) return;
    const float* xin = bufsel(xbuf);
    int f = lane * 4;
    float w00 = We[(f + 0) * 3], w01 = We[(f + 0) * 3 + 1], w02 = We[(f + 0) * 3 + 2];
    float w10 = We[(f + 1) * 3], w11 = We[(f + 1) * 3 + 1], w12 = We[(f + 1) * 3 + 2];
    float w20 = We[(f + 2) * 3], w21 = We[(f + 2) * 3 + 1], w22 = We[(f + 2) * 3 + 2];
    float w30 = We[(f + 3) * 3], w31 = We[(f + 3) * 3 + 1], w32 = We[(f + 3) * 3 + 2];
    float b0 = be[f + 0], b1 = be[f + 1], b2 = be[f + 2], b3 = be[f + 3];
    float a0 = 0.f, a1 = 0.f, a2 = 0.f, a3 = 0.f;
    int e0 = d_off[gw], e1 = d_off[gw + 1];
    for (int e = e0; e < e1; e++) {
        float4 r = __ldg(&d_erec[e]);
        int s = __float_as_int(r.x);
        float4 xs = __ldg((const float4*)(xin + (size_t)s * DD + f));
        a0 += fmaxf(xs.x + fmaf(w00, r.y, fmaf(w01, r.z, fmaf(w02, r.w, b0))), 0.f);
        a1 += fmaxf(xs.y + fmaf(w10, r.y, fmaf(w11, r.z, fmaf(w12, r.w, b1))), 0.f);
        a2 += fmaxf(xs.z + fmaf(w20, r.y, fmaf(w21, r.z, fmaf(w22, r.w, b2))), 0.f);
        a3 += fmaxf(xs.w + fmaf(w30, r.y, fmaf(w31, r.z, fmaf(w32, r.w, b3))), 0.f);
    }
    float4 xn = *(const float4*)(xin + (size_t)gw * DD + f);
    float4 o = make_float4(xn.x + a0, xn.y + a1, xn.z + a2, xn.w + a3);
    *(float4*)(d_bufA + (size_t)gw * DD + f) = o;
}

// ---------------- BN fold + stat reset ----------------
__global__ void k_bn(const float* __restrict__ g, const float* __restrict__ b) {
    int d = threadIdx.x;
    float inv_n = 1.0f / (float)NN;
    float mu = d_colsum[d] * inv_n;
    float var = d_colsq[d] * inv_n - mu * mu;
    float a = g[d] * rsqrtf(var + 1e-5f);
    d_alpha[d] = a;
    d_beta[d] = fmaf(-mu, a, b[d]);
    d_colsum[d] = 0.f;
    d_colsq[d] = 0.f;
}

// ---------------- GEMM1 for layer0 (din=9), with BN stats ----------------
__global__ void k_gemm9(const float* __restrict__ W1) {
    __shared__ float sA[64][17];
    int d = threadIdx.x;
    float w[9];
#pragma unroll
    for (int k = 0; k < 9; k++) w[k] = W1[d * 9 + k];
    int r0 = blockIdx.x * 64;
    for (int i = d; i < 64 * 16; i += 128) {
        int rr = i >> 4, cc = i & 15;
        int r = r0 + rr;
        sA[rr][cc] = (r < NN && cc < 9) ? d_bufA9[r * 16 + cc] : 0.f;
    }
    __syncthreads();
    float cs = 0.f, cq = 0.f;
    int rmax = min(64, NN - r0);
    for (int rr = 0; rr < rmax; rr++) {
        float h = 0.f;
#pragma unroll
        for (int k = 0; k < 9; k++) h = fmaf(sA[rr][k], w[k], h);
        d_bufH[(size_t)(r0 + rr) * DD + d] = h;
        cs += h;
        cq += h * h;
    }
    atomicAdd(&d_colsum[d], cs);
    atomicAdd(&d_colsq[d], cq);
}

// ---------------- bf16-split tensor-core GEMM (mma.sync m16n8k16) ----------------
// 64(M) x 128(N) tile, K=128. 8 warps in 2(m) x 4(n): warp = 32 rows x 32 cols.
// D = Ah*Bh + Ah*Bl + Al*Bh (fp32 acc).  W comes pre-swizzled bf16 hi/lo (d_WH/d_WL).
// BN=1: C = relu( relu(alpha*A+beta) @ W^T + bias );  STATS=1: accumulate colsum/colsq of C.
#define SMEM_MMA (96 * 1024 + 1024)

template <int BN, int STATS>
__global__ void __launch_bounds__(256, 2) k_mma(int abuf, int cbuf, int widx,
                                                const float* __restrict__ bias) {
    extern __shared__ char dynsm[];
    __shared__ float sSum[2][128], sSq[2][128];
    uint32_t sb = (smem_u32(dynsm) + 1023) & ~1023u;
    uint32_t AH = sb, AL = sb + 16384, BH = sb + 32768, BL = sb + 65536;

    const float* A = bufsel(abuf);
    float* C = bufsel(cbuf);

    int tid = threadIdx.x;
    int warp = tid >> 5, lane = tid & 31;
    int rowBase = blockIdx.x * 64;

    // ---- A: fp32 -> bf16 hi/lo, swizzled [64][128] ----
#pragma unroll
    for (int it = 0; it < 8; it++) {
        int idx = tid + it * 256;
        int r = idx >> 5, quad = idx & 31;
        int rg = rowBase + r;
        float4 v = (rg < NN) ? *(const float4*)(A + (size_t)rg * DD + quad * 4)
                             : make_float4(0.f, 0.f, 0.f, 0.f);
        if (BN) {
            float4 al4 = *(const float4*)(&d_alpha[quad * 4]);
            float4 be4 = *(const float4*)(&d_beta[quad * 4]);
            v.x = fmaxf(fmaf(v.x, al4.x, be4.x), 0.f);
            v.y = fmaxf(fmaf(v.y, al4.y, be4.y), 0.f);
            v.z = fmaxf(fmaf(v.z, al4.z, be4.z), 0.f);
            v.w = fmaxf(fmaf(v.w, al4.w, be4.w), 0.f);
        }
        uint32_t sa = swz((uint32_t)(r * 256 + quad * 8));
        uint32_t h0 = pkbf(v.x, v.y), h1 = pkbf(v.z, v.w);
        uint32_t l0 = pkbf(v.x - unlo(h0), v.y - unhi(h0));
        uint32_t l1 = pkbf(v.z - unlo(h1), v.w - unhi(h1));
        sts32(AH + sa, h0); sts32(AH + sa + 4, h1);
        sts32(AL + sa, l0); sts32(AL + sa + 4, l1);
    }
    // ---- B: straight copy of pre-swizzled bf16 hi/lo (32KB each) ----
    {
        const uint4* wh = (const uint4*)(d_WH + widx * 8192);
        const uint4* wl = (const uint4*)(d_WL + widx * 8192);
#pragma unroll
        for (int it = 0; it < 8; it++) {
            int i = tid + it * 256;          // 0..2047 uint4
            sts128(BH + i * 16, __ldg(wh + i));
            sts128(BL + i * 16, __ldg(wl + i));
        }
    }
    __syncthreads();

    int m0 = (warp >> 2) * 32;   // 0,32
    int n0 = (warp & 3) * 32;    // 0,32,64,96

    float acc[2][4][4];
#pragma unroll
    for (int mt = 0; mt < 2; mt++)
#pragma unroll
        for (int nt = 0; nt < 4; nt++)
#pragma unroll
            for (int j = 0; j < 4; j++) acc[mt][nt][j] = 0.f;

    int mi = lane >> 3, ri = lane & 7;
    int arow = m0 + (mi & 1) * 8 + ri;          // + mt*16
    uint32_t axor = (uint32_t)((arow & 7) << 4);
    int akc = (mi >> 1) * 8;
    int brow = n0 + (mi >> 1) * 8 + ri;         // + nt2*16
    uint32_t bxor = (uint32_t)((brow & 7) << 4);
    int bkc = (mi & 1) * 8;

#pragma unroll
    for (int kc = 0; kc < 8; kc++) {
        int k0 = kc * 16;
        uint32_t aH[2][4], aL[2][4];
#pragma unroll
        for (int mt = 0; mt < 2; mt++) {
            uint32_t off = (uint32_t)((arow + mt * 16) * 256) +
                           (((uint32_t)((k0 + akc) * 2)) ^ axor);
            ldsm4(aH[mt], AH + off);
            ldsm4(aL[mt], AL + off);
        }
        uint32_t bHf[4][2], bLf[4][2];
#pragma unroll
        for (int nt2 = 0; nt2 < 2; nt2++) {
            uint32_t off = (uint32_t)((brow + nt2 * 16) * 256) +
                           (((uint32_t)((k0 + bkc) * 2)) ^ bxor);
            uint32_t t[4];
            ldsm4(t, BH + off);
            bHf[nt2 * 2][0] = t[0]; bHf[nt2 * 2][1] = t[1];
            bHf[nt2 * 2 + 1][0] = t[2]; bHf[nt2 * 2 + 1][1] = t[3];
            ldsm4(t, BL + off);
            bLf[nt2 * 2][0] = t[0]; bLf[nt2 * 2][1] = t[1];
            bLf[nt2 * 2 + 1][0] = t[2]; bLf[nt2 * 2 + 1][1] = t[3];
        }
#pragma unroll
        for (int mt = 0; mt < 2; mt++)
#pragma unroll
            for (int nt = 0; nt < 4; nt++) {
                mma_bf16(acc[mt][nt], aH[mt], bHf[nt]);
                mma_bf16(acc[mt][nt], aH[mt], bLf[nt]);
                mma_bf16(acc[mt][nt], aL[mt], bHf[nt]);
            }
    }

    // ---- epilogue: store (+ optional bias/relu), optional column stats ----
    int g = lane >> 2, cpair = (lane & 3) * 2;
    float ps[4][2], pq[4][2];
    if (STATS) {
#pragma unroll
        for (int nt = 0; nt < 4; nt++) { ps[nt][0] = ps[nt][1] = pq[nt][0] = pq[nt][1] = 0.f; }
    }
#pragma unroll
    for (int mt = 0; mt < 2; mt++) {
#pragma unroll
        for (int half = 0; half < 2; half++) {
            int rg = rowBase + m0 + mt * 16 + g + half * 8;
            if (rg >= NN) continue;
#pragma unroll
            for (int nt = 0; nt < 4; nt++) {
                int col = n0 + nt * 8 + cpair;
                float v0 = acc[mt][nt][half * 2 + 0];
                float v1 = acc[mt][nt][half * 2 + 1];
                if (BN) {
                    v0 = fmaxf(v0 + __ldg(bias + col), 0.f);
                    v1 = fmaxf(v1 + __ldg(bias + col + 1), 0.f);
                }
                if (STATS) {
                    ps[nt][0] += v0; ps[nt][1] += v1;
                    pq[nt][0] += v0 * v0; pq[nt][1] += v1 * v1;
                }
                *(float2*)(C + (size_t)rg * DD + col) = make_float2(v0, v1);
            }
        }
    }
    if (STATS) {
#pragma unroll
        for (int nt = 0; nt < 4; nt++)
#pragma unroll
            for (int j = 0; j < 2; j++)
#pragma unroll
                for (int o = 4; o < 32; o <<= 1) {
                    ps[nt][j] += __shfl_xor_sync(0xffffffffu, ps[nt][j], o);
                    pq[nt][j] += __shfl_xor_sync(0xffffffffu, pq[nt][j], o);
                }
        if (g == 0) {
            int wm = warp >> 2;
#pragma unroll
            for (int nt = 0; nt < 4; nt++) {
                int col = n0 + nt * 8 + cpair;
                sSum[wm][col] = ps[nt][0]; sSum[wm][col + 1] = ps[nt][1];
                sSq[wm][col] = pq[nt][0];  sSq[wm][col + 1] = pq[nt][1];
            }
        }
        __syncthreads();
        if (tid < 128) {
            atomicAdd(&d_colsum[tid], sSum[0][tid] + sSum[1][tid]);
            atomicAdd(&d_colsq[tid], sSq[0][tid] + sSq[1][tid]);
        }
    }
}

// ---------------- pooling: all 3 layers in one kernel ----------------
__global__ void k_pool(float* __restrict__ out) {
    int g = blockIdx.x;
    int t = threadIdx.x;           // 0..383
    int layer = t >> 7, d = t & 127;
    const float* B = (layer == 0) ? d_bufX0 : (layer == 1) ? d_bufX1 : d_bufX2;
    int n0 = d_gstart[g], n1 = d_gstart[g + 1];
    float s = 0.f;
    for (int n = n0; n < n1; n++) s += B[(size_t)n * DD + d];
    out[(size_t)g * 384 + layer * 128 + d] = s;
}

// ---------------- launch ----------------
extern "C" void kernel_launch(void* const* d_in, const int* in_sizes, int n_in,
                              void* d_out, int out_size) {
    const float* x = (const float*)d_in[0];
    const int* ei = (const int*)d_in[1];
    const float* ea = (const float*)d_in[2];
    const int* batch = (const int*)d_in[3];
    const float* P[21];
    for (int i = 0; i < 21; i++) P[i] = (const float*)d_in[4 + i];
    float* out = (float*)d_out;
    const int* src = ei;
    const int* dst = ei + EE;

    cudaFuncSetAttribute(k_mma<0, 0>, cudaFuncAttributeMaxDynamicSharedMemorySize, SMEM_MMA);
    cudaFuncSetAttribute(k_mma<0, 1>, cudaFuncAttributeMaxDynamicSharedMemorySize, SMEM_MMA);
    cudaFuncSetAttribute(k_mma<1, 0>, cudaFuncAttributeMaxDynamicSharedMemorySize, SMEM_MMA);

    const int mma_grid = (NN + 63) / 64;  // 782

    // 1-3: setup
    k_init<<<(NN + 1 + 255) / 256, 256>>>();
    k_wconv<<<5, 256>>>(P[5], P[9], P[12], P[16], P[19]);
    k_hist<<<(EE + 255) / 256, 256>>>(dst);
    // 4: PROFILING PROBE — full-size k_mma on stale bufA; bufH fully overwritten by
    //    k_gemm9 below, so results are unaffected and the launch stays deterministic.
    k_mma<0, 0><<<mma_grid, 256, SMEM_MMA>>>(0, 1, 0, nullptr);
    // 5-9: CSR + graph bounds
    k_gbound<<<1, 512>>>(batch);
    k_scan1<<<NCH, 1024>>>();
    k_scan2<<<1, 1>>>();
    k_scan3<<<NCH, 1024>>>();
    k_scatter<<<(EE + 255) / 256, 256>>>(src, dst, ea);

    // ---- layer 0 (din = 9) ----
    k_agg9<<<(NN + 7) / 8, 256>>>(x, P[0], P[1]);
    k_gemm9<<<(NN + 63) / 64, 128>>>(P[2]);
    k_bn<<<1, 128>>>(P[3], P[4]);
    k_mma<1, 0><<<mma_grid, 256, SMEM_MMA>>>(1, 2, 0, P[6]);

    // ---- layer 1 ----
    k_agg128<<<(NN + 7) / 8, 256>>>(2, P[7], P[8]);
    k_mma<0, 1><<<mma_grid, 256, SMEM_MMA>>>(0, 1, 1, nullptr);
    k_bn<<<1, 128>>>(P[10], P[11]);
    k_mma<1, 0><<<mma_grid, 256, SMEM_MMA>>>(1, 3, 2, P[13]);

    // ---- layer 2 ----
    k_agg128<<<(NN + 7) / 8, 256>>>(3, P[14], P[15]);
    k_mma<0, 1><<<mma_grid, 256, SMEM_MMA>>>(0, 1, 3, nullptr);
    k_bn<<<1, 128>>>(P[17], P[18]);
    k_mma<1, 0><<<mma_grid, 256, SMEM_MMA>>>(1, 4, 4, P[20]);

    // ---- pooled outputs ----
    k_pool<<<GG, 384>>>(out);
}